// round 1
// baseline (speedup 1.0000x reference)
#include <cuda_runtime.h>
#include <cstdint>
#include <math.h>

// ---------------- problem constants ----------------
#define B_    4
#define N_    8192
#define D_    1024
#define H_    8
#define DH_   64
#define HID_  512
#define WIN_  128
#define NQ_   1024
#define NKV_  2048
#define NITER_ 50
#define ROWS_ (B_*N_)          // 32768
#define SCALE_ 0.125f

// ---------------- device scratch (static; no allocations allowed) ----------
__device__ float g_xn  [ (size_t)ROWS_*D_      ];  // light rmsnorm(x)
__device__ float g_q   [ (size_t)ROWS_*HID_    ];  // light q
__device__ float g_kv  [ (size_t)ROWS_*2*HID_  ];  // light k|v
__device__ float g_ao  [ (size_t)ROWS_*HID_    ];  // light attn out (pre-wo)
__device__ float g_s   [ (size_t)2*ROWS_       ];  // routing scores (q route, kv route)
__device__ int   g_idxq[ B_*NQ_  ];
__device__ int   g_idxkv[B_*NKV_ ];
__device__ float g_xqn [ (size_t)B_*NQ_*D_     ];
__device__ float g_ctxn[ (size_t)B_*NKV_*D_    ];
__device__ float g_qh  [ (size_t)B_*NQ_*HID_   ];
__device__ float g_kvh [ (size_t)B_*NKV_*2*HID_];
__device__ float g_aoh [ (size_t)B_*NQ_*HID_   ];

// ---------------- block reduction helper ----------------
// op: 0 = sum, 1 = max. Includes trailing sync so `sh` is reusable.
__device__ __forceinline__ float block_reduce(float v, float* sh, int op) {
    int lane = threadIdx.x & 31, w = threadIdx.x >> 5, nw = blockDim.x >> 5;
    #pragma unroll
    for (int o = 16; o; o >>= 1) {
        float t = __shfl_xor_sync(0xFFFFFFFFu, v, o);
        v = op ? fmaxf(v, t) : (v + t);
    }
    if (lane == 0) sh[w] = v;
    __syncthreads();
    if (w == 0) {
        v = (lane < nw) ? sh[lane] : (op ? -INFINITY : 0.0f);
        #pragma unroll
        for (int o = 16; o; o >>= 1) {
            float t = __shfl_xor_sync(0xFFFFFFFFu, v, o);
            v = op ? fmaxf(v, t) : (v + t);
        }
        if (lane == 0) sh[0] = v;
    }
    __syncthreads();
    v = sh[0];
    __syncthreads();
    return v;
}

// ---------------- K1: light rmsnorm + routing logits ----------------
// one block per row (256 threads, 1 float4 per thread)
__global__ void __launch_bounds__(256) prep_kernel(
    const float* __restrict__ x, const float* __restrict__ gamma,
    const float* __restrict__ qtok, const float* __restrict__ kvtok)
{
    __shared__ float sh[32];
    int row = blockIdx.x, tid = threadIdx.x;
    const float4 v  = ((const float4*)(x + (size_t)row*D_))[tid];
    const float4 qt = ((const float4*)qtok)[tid];
    const float4 kt = ((const float4*)kvtok)[tid];
    float ss = v.x*v.x + v.y*v.y + v.z*v.z + v.w*v.w;
    float dq = v.x*qt.x + v.y*qt.y + v.z*qt.z + v.w*qt.w;
    float dk = v.x*kt.x + v.y*kt.y + v.z*kt.z + v.w*kt.w;
    ss = block_reduce(ss, sh, 0);
    dq = block_reduce(dq, sh, 0);
    dk = block_reduce(dk, sh, 0);
    float inv = 32.0f / fmaxf(sqrtf(ss), 1e-12f);
    const float4 g = ((const float4*)gamma)[tid];
    float4 o;
    o.x = v.x*inv*g.x; o.y = v.y*inv*g.y; o.z = v.z*inv*g.z; o.w = v.w*inv*g.w;
    ((float4*)(g_xn + (size_t)row*D_))[tid] = o;
    if (tid == 0) { g_s[row] = dq; g_s[ROWS_ + row] = dk; }
}

// ---------------- K2: coor-descent + top-k (set) selection ----------------
// grid: 8 blocks = (route in {0=q,1=kv}) x (batch in 0..3). 1024 threads.
// dynamic smem: ss[8192] f32 | bb[8192] f32 | keys[8192] u64  = 128 KB
__global__ void __launch_bounds__(1024) routing_kernel()
{
    extern __shared__ float smr[];
    float* ss = smr;
    float* bb = smr + N_;
    unsigned long long* keys = (unsigned long long*)(smr + 2*N_);
    __shared__ float sh[32];
    int tid = threadIdx.x;
    int b = blockIdx.x & 3;
    int route = blockIdx.x >> 2;
    const float* sp = g_s + (size_t)route*ROWS_ + (size_t)b*N_;
    for (int i = tid; i < N_; i += 1024) { float v = sp[i]; ss[i] = v; bb[i] = -v; }
    __syncthreads();
    const float logk = route ? logf(2304.0f) : logf(1152.0f);
    float a = 0.0f;
    for (int it = 0; it < NITER_; it++) {
        float lm = -INFINITY;
        for (int i = tid; i < N_; i += 1024) lm = fmaxf(lm, ss[i] + bb[i]);
        float m = block_reduce(lm, sh, 1);
        float lsum = 0.0f;
        for (int i = tid; i < N_; i += 1024) lsum += expf(ss[i] + bb[i] - m);
        float sum = block_reduce(lsum, sh, 0);
        a = logk - (m + logf(sum));
        // bb[i] is owned exclusively by thread (i % 1024); reduction synced above
        for (int i = tid; i < N_; i += 1024) bb[i] = -fmaxf(ss[i] + a, 0.0f);
    }
    __syncthreads();
    // scores + sort keys: (score_bits desc, index asc) == lax.top_k semantics
    for (int i = tid; i < N_; i += 1024) {
        float sc = expf(fminf(ss[i] + a, 0.0f));   // exp(s+a+b) = exp(min(s+a,0))
        keys[i] = ((unsigned long long)__float_as_uint(sc) << 32)
                | (unsigned long long)(0xFFFFFFFFu - (unsigned)i);
    }
    __syncthreads();
    // bitonic sort descending, n = 8192, 4 pairs/thread
    for (int size = 2; size <= N_; size <<= 1) {
        for (int stride = size >> 1; stride > 0; stride >>= 1) {
            #pragma unroll
            for (int r = 0; r < N_/2/1024; r++) {
                int t = tid + r*1024;
                int pos = 2*t - (t & (stride - 1));
                bool dir = ((pos & size) == 0);            // descending runs
                unsigned long long A = keys[pos], Bv = keys[pos + stride];
                if ((A < Bv) == dir) { keys[pos] = Bv; keys[pos + stride] = A; }
            }
            __syncthreads();
        }
    }
    // extract selected indices, sort ascending for coalesced gather
    int sel = route ? NKV_ : NQ_;
    unsigned* ids = (unsigned*)bb;
    for (int i = tid; i < sel; i += 1024)
        ids[i] = 0xFFFFFFFFu - (unsigned)(keys[i] & 0xFFFFFFFFull);
    __syncthreads();
    for (int size = 2; size <= sel; size <<= 1) {
        for (int stride = size >> 1; stride > 0; stride >>= 1) {
            if (tid < sel/2) {
                int pos = 2*tid - (tid & (stride - 1));
                bool dir = ((pos & size) != 0);            // ascending
                unsigned A = ids[pos], Bv = ids[pos + stride];
                if ((A < Bv) == dir) { ids[pos] = Bv; ids[pos + stride] = A; }
            }
            __syncthreads();
        }
    }
    int* outp = route ? (g_idxkv + b*NKV_) : (g_idxq + b*NQ_);
    for (int i = tid; i < sel; i += 1024) outp[i] = (int)ids[i];
}

// ---------------- K3: gather + heavy rmsnorm ----------------
__global__ void __launch_bounds__(256) gather_norm_kernel(
    const float* __restrict__ x, const float* __restrict__ gamma)
{
    __shared__ float sh[32];
    int bid = blockIdx.x, tid = threadIdx.x;
    int b, src; float* dst;
    if (bid < B_*NQ_) { b = bid >> 10; src = g_idxq[bid];  dst = g_xqn  + (size_t)bid*D_; }
    else { int j = bid - B_*NQ_; b = j >> 11; src = g_idxkv[j]; dst = g_ctxn + (size_t)j*D_; }
    const float4 v = ((const float4*)(x + ((size_t)b*N_ + src)*D_))[tid];
    float ssum = block_reduce(v.x*v.x + v.y*v.y + v.z*v.z + v.w*v.w, sh, 0);
    float inv = 32.0f / fmaxf(sqrtf(ssum), 1e-12f);
    const float4 g = ((const float4*)gamma)[tid];
    float4 o;
    o.x = v.x*inv*g.x; o.y = v.y*inv*g.y; o.z = v.z*inv*g.z; o.w = v.w*inv*g.w;
    ((float4*)dst)[tid] = o;
}

// ---------------- K4: generic SGEMM 128x128x16, 256 thr, 8x8 per thread ----
// C[M,N] = A[M,K] @ B      (transB=0: B is [K,N] row-major; transB=1: B is [N,K])
// mode 0: C[r*N + c] = acc      mode 2: d_out[(b*8192 + idxq[b,qi])*1024 + c] += acc
#define BM 128
#define BN 128
#define BK 16
__global__ void __launch_bounds__(256) sgemm_kernel(
    const float* __restrict__ A, const float* __restrict__ B, float* __restrict__ C,
    int M, int Ncols, int K, int transB, int mode, const int* __restrict__ idxmap)
{
    __shared__ float As[BK][BM];
    __shared__ float Bs[BK][BN];
    int tid = threadIdx.x;
    int bm = blockIdx.y * BM;
    int bn = blockIdx.x * BN;
    int tm = (tid >> 4) * 8;
    int tn = (tid & 15) * 8;
    float acc[8][8] = {};
    for (int k0 = 0; k0 < K; k0 += BK) {
        #pragma unroll
        for (int i = 0; i < 2; i++) {        // A tile: 128 rows x 16 cols
            int l = tid + i*256;
            int r = l >> 2, c4 = l & 3;
            float4 v = *(const float4*)(A + (size_t)(bm + r)*K + k0 + c4*4);
            As[c4*4+0][r] = v.x; As[c4*4+1][r] = v.y;
            As[c4*4+2][r] = v.z; As[c4*4+3][r] = v.w;
        }
        if (!transB) {
            #pragma unroll
            for (int i = 0; i < 2; i++) {    // B tile: 16 rows x 128 cols
                int l = tid + i*256;
                int r = l >> 5, c4 = l & 31;
                float4 v = *(const float4*)(B + (size_t)(k0 + r)*Ncols + bn + c4*4);
                *(float4*)&Bs[r][c4*4] = v;
            }
        } else {
            #pragma unroll
            for (int i = 0; i < 2; i++) {    // B^T tile: 128 n-rows x 16 k-cols
                int l = tid + i*256;
                int r = l >> 2, c4 = l & 3;
                float4 v = *(const float4*)(B + (size_t)(bn + r)*K + k0 + c4*4);
                Bs[c4*4+0][r] = v.x; Bs[c4*4+1][r] = v.y;
                Bs[c4*4+2][r] = v.z; Bs[c4*4+3][r] = v.w;
            }
        }
        __syncthreads();
        #pragma unroll
        for (int kk = 0; kk < BK; kk++) {
            float ra[8], rb[8];
            *(float4*)&ra[0] = *(const float4*)&As[kk][tm];
            *(float4*)&ra[4] = *(const float4*)&As[kk][tm+4];
            *(float4*)&rb[0] = *(const float4*)&Bs[kk][tn];
            *(float4*)&rb[4] = *(const float4*)&Bs[kk][tn+4];
            #pragma unroll
            for (int i = 0; i < 8; i++)
                #pragma unroll
                for (int j = 0; j < 8; j++)
                    acc[i][j] = fmaf(ra[i], rb[j], acc[i][j]);
        }
        __syncthreads();
    }
    #pragma unroll
    for (int i = 0; i < 8; i++) {
        int r = bm + tm + i;
        float* cp;
        if (mode == 0) {
            cp = C + (size_t)r*Ncols + bn + tn;
            float4 v0 = {acc[i][0], acc[i][1], acc[i][2], acc[i][3]};
            float4 v1 = {acc[i][4], acc[i][5], acc[i][6], acc[i][7]};
            *(float4*)cp = v0; *(float4*)(cp + 4) = v1;
        } else {
            int bb2 = r >> 10, qi = r & 1023;
            int orow = bb2*N_ + idxmap[bb2*NQ_ + qi];
            cp = C + (size_t)orow*D_ + bn + tn;
            float4 v0 = *(float4*)cp;
            v0.x += acc[i][0]; v0.y += acc[i][1]; v0.z += acc[i][2]; v0.w += acc[i][3];
            *(float4*)cp = v0;
            float4 v1 = *(float4*)(cp + 4);
            v1.x += acc[i][4]; v1.y += acc[i][5]; v1.z += acc[i][6]; v1.w += acc[i][7];
            *(float4*)(cp + 4) = v1;
        }
    }
}

// ---------------- K5: flash attention (shared by light & heavy) ----------------
// 128 threads = 128 query rows. KV tiles of 64. Scores staged in padded smem.
// mode 0 = light (kv = same 128-token window), mode 1 = heavy (kv = 2048 routed)
#define KT 64
#define FLASH_SMEM ((KT*DH_*2 + 128*65) * 4)
__global__ void __launch_bounds__(128) flash_kernel(
    const float* __restrict__ Q, const float* __restrict__ K,
    const float* __restrict__ V, float* __restrict__ O, int mode)
{
    extern __shared__ float sm[];
    float* ks = sm;
    float* vs = sm + KT*DH_;
    float* sc = sm + 2*KT*DH_;   // [128][65] padded
    int tid = threadIdx.x;
    int qRow0, kvRow0, kvLen, qcol, kcol, vcol, ocol;
    if (mode == 0) {
        int h = blockIdx.x & 7, w = (blockIdx.x >> 3) & 63, b = blockIdx.x >> 9;
        qRow0 = b*N_ + w*WIN_; kvRow0 = qRow0; kvLen = WIN_;
        qcol = h*DH_; kcol = h*DH_; vcol = HID_ + h*DH_; ocol = h*DH_;
    } else {
        int h = blockIdx.x & 7, t = (blockIdx.x >> 3) & 7, b = blockIdx.x >> 6;
        qRow0 = b*NQ_ + t*128; kvRow0 = b*NKV_; kvLen = NKV_;
        qcol = h*DH_; kcol = h*2*DH_; vcol = h*2*DH_ + DH_; ocol = h*DH_;
    }
    const int qStride = HID_, kvStride = 2*HID_, oStride = HID_;

    float qr[DH_];
    {
        const float* qp = Q + (size_t)(qRow0 + tid)*qStride + qcol;
        #pragma unroll
        for (int d4 = 0; d4 < 16; d4++) {
            float4 v = *(const float4*)(qp + d4*4);
            qr[d4*4+0] = v.x*SCALE_; qr[d4*4+1] = v.y*SCALE_;
            qr[d4*4+2] = v.z*SCALE_; qr[d4*4+3] = v.w*SCALE_;
        }
    }
    float m = -INFINITY, l = 0.0f;
    float acc[DH_] = {};
    for (int t0 = 0; t0 < kvLen; t0 += KT) {
        #pragma unroll
        for (int i = 0; i < 8; i++) {        // 64x64 k + v tiles
            int l4 = tid + i*128;
            int r = l4 >> 4, c4 = l4 & 15;
            const float* kp = K + (size_t)(kvRow0 + t0 + r)*kvStride + kcol;
            const float* vp = V + (size_t)(kvRow0 + t0 + r)*kvStride + vcol;
            *(float4*)&ks[r*DH_ + c4*4] = *(const float4*)(kp + c4*4);
            *(float4*)&vs[r*DH_ + c4*4] = *(const float4*)(vp + c4*4);
        }
        __syncthreads();
        float tmax = -INFINITY;
        #pragma unroll 2
        for (int j = 0; j < KT; j++) {
            float s0 = 0, s1 = 0, s2 = 0, s3 = 0;
            const float4* kp4 = (const float4*)(ks + j*DH_);
            #pragma unroll
            for (int d4 = 0; d4 < 16; d4++) {
                float4 kv4 = kp4[d4];
                s0 = fmaf(qr[d4*4+0], kv4.x, s0);
                s1 = fmaf(qr[d4*4+1], kv4.y, s1);
                s2 = fmaf(qr[d4*4+2], kv4.z, s2);
                s3 = fmaf(qr[d4*4+3], kv4.w, s3);
            }
            float s = (s0 + s1) + (s2 + s3);
            sc[tid*65 + j] = s;
            tmax = fmaxf(tmax, s);
        }
        float mn = fmaxf(m, tmax);
        float corr = expf(m - mn);           // first tile: exp(-inf)=0
        l *= corr;
        #pragma unroll
        for (int d = 0; d < DH_; d++) acc[d] *= corr;
        #pragma unroll 2
        for (int j = 0; j < KT; j++) {
            float p = expf(sc[tid*65 + j] - mn);
            l += p;
            const float4* vp4 = (const float4*)(vs + j*DH_);
            #pragma unroll
            for (int d4 = 0; d4 < 16; d4++) {
                float4 vv = vp4[d4];
                acc[d4*4+0] = fmaf(p, vv.x, acc[d4*4+0]);
                acc[d4*4+1] = fmaf(p, vv.y, acc[d4*4+1]);
                acc[d4*4+2] = fmaf(p, vv.z, acc[d4*4+2]);
                acc[d4*4+3] = fmaf(p, vv.w, acc[d4*4+3]);
            }
        }
        m = mn;
        __syncthreads();
    }
    float invl = 1.0f / l;
    float* op = O + (size_t)(qRow0 + tid)*oStride + ocol;
    #pragma unroll
    for (int d4 = 0; d4 < 16; d4++) {
        float4 o4 = {acc[d4*4+0]*invl, acc[d4*4+1]*invl,
                     acc[d4*4+2]*invl, acc[d4*4+3]*invl};
        *(float4*)(op + d4*4) = o4;
    }
}

// ---------------- host launch ----------------
extern "C" void kernel_launch(void* const* d_in, const int* in_sizes, int n_in,
                              void* d_out, int out_size)
{
    const float* x        = (const float*)d_in[0];
    const float* gammaL   = (const float*)d_in[1];
    const float* wqL      = (const float*)d_in[2];
    const float* wkvL     = (const float*)d_in[3];
    const float* woL      = (const float*)d_in[4];
    const float* qtok     = (const float*)d_in[5];
    const float* kvtok    = (const float*)d_in[6];
    const float* gammaH   = (const float*)d_in[7];
    const float* wqH      = (const float*)d_in[8];
    const float* wkvH     = (const float*)d_in[9];
    const float* woH      = (const float*)d_in[10];
    float* out = (float*)d_out;

    float *p_xn, *p_q, *p_kv, *p_ao, *p_xqn, *p_ctxn, *p_qh, *p_kvh, *p_aoh;
    int *p_idxq, *p_idxkv;
    cudaGetSymbolAddress((void**)&p_xn,   g_xn);
    cudaGetSymbolAddress((void**)&p_q,    g_q);
    cudaGetSymbolAddress((void**)&p_kv,   g_kv);
    cudaGetSymbolAddress((void**)&p_ao,   g_ao);
    cudaGetSymbolAddress((void**)&p_xqn,  g_xqn);
    cudaGetSymbolAddress((void**)&p_ctxn, g_ctxn);
    cudaGetSymbolAddress((void**)&p_qh,   g_qh);
    cudaGetSymbolAddress((void**)&p_kvh,  g_kvh);
    cudaGetSymbolAddress((void**)&p_aoh,  g_aoh);
    cudaGetSymbolAddress((void**)&p_idxq, g_idxq);
    cudaGetSymbolAddress((void**)&p_idxkv,g_idxkv);

    cudaFuncSetAttribute(routing_kernel, cudaFuncAttributeMaxDynamicSharedMemorySize, 131072);
    cudaFuncSetAttribute(flash_kernel,   cudaFuncAttributeMaxDynamicSharedMemorySize, FLASH_SMEM);

    // light rmsnorm + routing logits
    prep_kernel<<<ROWS_, 256>>>(x, gammaL, qtok, kvtok);
    // routing: coor-descent + top-k sets
    routing_kernel<<<8, 1024, 131072>>>();
    // light GEMMs
    sgemm_kernel<<<dim3(HID_/BN,   ROWS_/BM), 256>>>(p_xn, wqL,  p_q,  ROWS_, HID_,   D_,   0, 0, nullptr);
    sgemm_kernel<<<dim3(2*HID_/BN, ROWS_/BM), 256>>>(p_xn, wkvL, p_kv, ROWS_, 2*HID_, D_,   0, 0, nullptr);
    // light windowed attention
    flash_kernel<<<B_*(N_/WIN_)*H_, 128, FLASH_SMEM>>>(p_q, p_kv, p_kv, p_ao, 0);
    // light output projection -> d_out (covers every row)
    sgemm_kernel<<<dim3(D_/BN, ROWS_/BM), 256>>>(p_ao, woL, out, ROWS_, D_, HID_, 0, 0, nullptr);
    // heavy gather + rmsnorm
    gather_norm_kernel<<<B_*NQ_ + B_*NKV_, 256>>>(x, gammaH);
    // heavy GEMMs (wkvH is [2*HID, D] torch layout -> B^T)
    sgemm_kernel<<<dim3(HID_/BN,   (B_*NQ_)/BM),  256>>>(p_xqn,  wqH,  p_qh,  B_*NQ_,  HID_,   D_, 0, 0, nullptr);
    sgemm_kernel<<<dim3(2*HID_/BN, (B_*NKV_)/BM), 256>>>(p_ctxn, wkvH, p_kvh, B_*NKV_, 2*HID_, D_, 1, 0, nullptr);
    // heavy flash attention
    flash_kernel<<<B_*(NQ_/128)*H_, 128, FLASH_SMEM>>>(p_qh, p_kvh, p_kvh, p_aoh, 1);
    // heavy output projection + scatter-add into d_out
    sgemm_kernel<<<dim3(D_/BN, (B_*NQ_)/BM), 256>>>(p_aoh, woH, out, B_*NQ_, D_, HID_, 0, 2, p_idxq);
}

// round 4
// speedup vs baseline: 1.4564x; 1.4564x over previous
#include <cuda_runtime.h>
#include <cuda_bf16.h>
#include <cstdint>
#include <math.h>

// ---------------- problem constants ----------------
#define B_    4
#define N_    8192
#define D_    1024
#define H_    8
#define DH_   64
#define HID_  512
#define WIN_  128
#define NQ_   1024
#define NKV_  2048
#define NITER_ 50
#define ROWS_ (B_*N_)          // 32768
#define SCALE_ 0.125f

// ---------------- device scratch ----------
// packed bf16 hi/lo operands (u32 per element = (hi<<16)|lo)
__device__ uint32_t c_xn  [ (size_t)ROWS_*D_      ];
__device__ uint32_t c_ao  [ (size_t)ROWS_*HID_    ];
__device__ uint32_t c_xqn [ (size_t)B_*NQ_*D_     ];
__device__ uint32_t c_ctxn[ (size_t)B_*NKV_*D_    ];
__device__ uint32_t c_aoh [ (size_t)B_*NQ_*HID_   ];
__device__ uint32_t c_wqL [ (size_t)HID_*D_   ];   // [N=512][K=1024]
__device__ uint32_t c_wkvL[ (size_t)2*HID_*D_ ];   // [1024][1024]
__device__ uint32_t c_woL [ (size_t)D_*HID_   ];   // [1024][512]
__device__ uint32_t c_wqH [ (size_t)HID_*D_   ];   // [512][1024]
__device__ uint32_t c_wkvH[ (size_t)2*HID_*D_ ];   // [1024][1024] (already [N][K])
__device__ uint32_t c_woH [ (size_t)D_*HID_   ];   // [1024][512]
// fp32 intermediates (flash attention I/O)
__device__ float g_q   [ (size_t)ROWS_*HID_    ];
__device__ float g_kv  [ (size_t)ROWS_*2*HID_  ];
__device__ float g_qh  [ (size_t)B_*NQ_*HID_   ];
__device__ float g_kvh [ (size_t)B_*NKV_*2*HID_];
__device__ float g_s   [ (size_t)2*ROWS_       ];
__device__ int   g_idxq[ B_*NQ_  ];
__device__ int   g_idxkv[B_*NKV_ ];

// ---------------- helpers ----------------
__device__ __forceinline__ uint32_t pack_hl(float x) {
    __nv_bfloat16 h = __float2bfloat16(x);
    float r = x - __bfloat162float(h);
    __nv_bfloat16 l = __float2bfloat16(r);
    return ((uint32_t)__bfloat16_as_ushort(h) << 16) | (uint32_t)__bfloat16_as_ushort(l);
}
__device__ __forceinline__ uint32_t prmt_(uint32_t a, uint32_t b, uint32_t s) {
    uint32_t d; asm("prmt.b32 %0,%1,%2,%3;" : "=r"(d) : "r"(a), "r"(b), "r"(s)); return d;
}
__device__ __forceinline__ void ldm4(uint32_t* r, uint32_t saddr) {
    asm volatile("ldmatrix.sync.aligned.m8n8.x4.shared.b16 {%0,%1,%2,%3}, [%4];"
        : "=r"(r[0]), "=r"(r[1]), "=r"(r[2]), "=r"(r[3]) : "r"(saddr));
}
__device__ __forceinline__ void mma16816(float* c, const uint32_t* a, uint32_t b0, uint32_t b1) {
    asm volatile("mma.sync.aligned.m16n8k16.row.col.f32.bf16.bf16.f32 "
        "{%0,%1,%2,%3}, {%4,%5,%6,%7}, {%8,%9}, {%0,%1,%2,%3};"
        : "+f"(c[0]), "+f"(c[1]), "+f"(c[2]), "+f"(c[3])
        : "r"(a[0]), "r"(a[1]), "r"(a[2]), "r"(a[3]), "r"(b0), "r"(b1));
}

// block reduction: op 0 = sum, 1 = max
__device__ __forceinline__ float block_reduce(float v, float* sh, int op) {
    int lane = threadIdx.x & 31, w = threadIdx.x >> 5, nw = blockDim.x >> 5;
    #pragma unroll
    for (int o = 16; o; o >>= 1) {
        float t = __shfl_xor_sync(0xFFFFFFFFu, v, o);
        v = op ? fmaxf(v, t) : (v + t);
    }
    if (lane == 0) sh[w] = v;
    __syncthreads();
    if (w == 0) {
        v = (lane < nw) ? sh[lane] : (op ? -INFINITY : 0.0f);
        #pragma unroll
        for (int o = 16; o; o >>= 1) {
            float t = __shfl_xor_sync(0xFFFFFFFFu, v, o);
            v = op ? fmaxf(v, t) : (v + t);
        }
        if (lane == 0) sh[0] = v;
    }
    __syncthreads();
    v = sh[0];
    __syncthreads();
    return v;
}

// ---------------- K1: light rmsnorm (-> packed) + routing logits ----------------
__global__ void __launch_bounds__(256) prep_kernel(
    const float* __restrict__ x, const float* __restrict__ gamma,
    const float* __restrict__ qtok, const float* __restrict__ kvtok)
{
    __shared__ float sh[32];
    int row = blockIdx.x, tid = threadIdx.x;
    const float4 v  = ((const float4*)(x + (size_t)row*D_))[tid];
    const float4 qt = ((const float4*)qtok)[tid];
    const float4 kt = ((const float4*)kvtok)[tid];
    float ss = v.x*v.x + v.y*v.y + v.z*v.z + v.w*v.w;
    float dq = v.x*qt.x + v.y*qt.y + v.z*qt.z + v.w*qt.w;
    float dk = v.x*kt.x + v.y*kt.y + v.z*kt.z + v.w*kt.w;
    ss = block_reduce(ss, sh, 0);
    dq = block_reduce(dq, sh, 0);
    dk = block_reduce(dk, sh, 0);
    float inv = 32.0f / fmaxf(sqrtf(ss), 1e-12f);
    const float4 g = ((const float4*)gamma)[tid];
    uint4 o;
    o.x = pack_hl(v.x*inv*g.x); o.y = pack_hl(v.y*inv*g.y);
    o.z = pack_hl(v.z*inv*g.z); o.w = pack_hl(v.w*inv*g.w);
    ((uint4*)(c_xn + (size_t)row*D_))[tid] = o;
    if (tid == 0) { g_s[row] = dq; g_s[ROWS_ + row] = dk; }
}

// ---------------- K2: coor-descent + top-k set selection ----------------
__global__ void __launch_bounds__(1024) routing_kernel()
{
    extern __shared__ float smr[];
    float* ss = smr;
    float* bb = smr + N_;
    unsigned long long* keys = (unsigned long long*)(smr + 2*N_);
    __shared__ float sh[32];
    int tid = threadIdx.x;
    int b = blockIdx.x & 3;
    int route = blockIdx.x >> 2;
    const float* sp = g_s + (size_t)route*ROWS_ + (size_t)b*N_;
    for (int i = tid; i < N_; i += 1024) { float v = sp[i]; ss[i] = v; bb[i] = -v; }
    __syncthreads();
    const float logk = route ? logf(2304.0f) : logf(1152.0f);
    float a = 0.0f;
    for (int it = 0; it < NITER_; it++) {
        float lm = -INFINITY;
        for (int i = tid; i < N_; i += 1024) lm = fmaxf(lm, ss[i] + bb[i]);
        float m = block_reduce(lm, sh, 1);
        float lsum = 0.0f;
        for (int i = tid; i < N_; i += 1024) lsum += expf(ss[i] + bb[i] - m);
        float sum = block_reduce(lsum, sh, 0);
        a = logk - (m + logf(sum));
        for (int i = tid; i < N_; i += 1024) bb[i] = -fmaxf(ss[i] + a, 0.0f);
    }
    __syncthreads();
    for (int i = tid; i < N_; i += 1024) {
        float sc = expf(fminf(ss[i] + a, 0.0f));
        keys[i] = ((unsigned long long)__float_as_uint(sc) << 32)
                | (unsigned long long)(0xFFFFFFFFu - (unsigned)i);
    }
    __syncthreads();
    for (int size = 2; size <= N_; size <<= 1) {
        for (int stride = size >> 1; stride > 0; stride >>= 1) {
            #pragma unroll
            for (int r = 0; r < N_/2/1024; r++) {
                int t = tid + r*1024;
                int pos = 2*t - (t & (stride - 1));
                bool dir = ((pos & size) == 0);
                unsigned long long A = keys[pos], Bv = keys[pos + stride];
                if ((A < Bv) == dir) { keys[pos] = Bv; keys[pos + stride] = A; }
            }
            __syncthreads();
        }
    }
    int sel = route ? NKV_ : NQ_;
    unsigned* ids = (unsigned*)bb;
    for (int i = tid; i < sel; i += 1024)
        ids[i] = 0xFFFFFFFFu - (unsigned)(keys[i] & 0xFFFFFFFFull);
    __syncthreads();
    for (int size = 2; size <= sel; size <<= 1) {
        for (int stride = size >> 1; stride > 0; stride >>= 1) {
            if (tid < sel/2) {
                int pos = 2*tid - (tid & (stride - 1));
                bool dir = ((pos & size) != 0);
                unsigned A = ids[pos], Bv = ids[pos + stride];
                if ((A < Bv) == dir) { ids[pos] = Bv; ids[pos + stride] = A; }
            }
            __syncthreads();
        }
    }
    int* outp = route ? (g_idxkv + b*NKV_) : (g_idxq + b*NQ_);
    for (int i = tid; i < sel; i += 1024) outp[i] = (int)ids[i];
}

// ---------------- K3: gather + heavy rmsnorm (-> packed) ----------------
__global__ void __launch_bounds__(256) gather_norm_kernel(
    const float* __restrict__ x, const float* __restrict__ gamma)
{
    __shared__ float sh[32];
    int bid = blockIdx.x, tid = threadIdx.x;
    int b, src; uint32_t* dst;
    if (bid < B_*NQ_) { b = bid >> 10; src = g_idxq[bid];  dst = c_xqn  + (size_t)bid*D_; }
    else { int j = bid - B_*NQ_; b = j >> 11; src = g_idxkv[j]; dst = c_ctxn + (size_t)j*D_; }
    const float4 v = ((const float4*)(x + ((size_t)b*N_ + src)*D_))[tid];
    float ssum = block_reduce(v.x*v.x + v.y*v.y + v.z*v.z + v.w*v.w, sh, 0);
    float inv = 32.0f / fmaxf(sqrtf(ssum), 1e-12f);
    const float4 g = ((const float4*)gamma)[tid];
    uint4 o;
    o.x = pack_hl(v.x*inv*g.x); o.y = pack_hl(v.y*inv*g.y);
    o.z = pack_hl(v.z*inv*g.z); o.w = pack_hl(v.w*inv*g.w);
    ((uint4*)dst)[tid] = o;
}

// ---------------- weight conversion kernels ----------------
__global__ void __launch_bounds__(256) convert_kernel(
    const float* __restrict__ in, uint32_t* __restrict__ out, int n4)
{
    int i = blockIdx.x*256 + threadIdx.x;
    if (i >= n4) return;
    float4 v = ((const float4*)in)[i];
    uint4 o = { pack_hl(v.x), pack_hl(v.y), pack_hl(v.z), pack_hl(v.w) };
    ((uint4*)out)[i] = o;
}
// transpose-convert: in [K][N] fp32 -> out [N][K] packed
__global__ void __launch_bounds__(256) wconvT_kernel(
    const float* __restrict__ in, uint32_t* __restrict__ out, int K, int N)
{
    __shared__ float t[32][33];
    int tx = threadIdx.x, ty = threadIdx.y;          // 32 x 8
    int n0 = blockIdx.x*32, k0 = blockIdx.y*32;
    #pragma unroll
    for (int i = 0; i < 4; i++)
        t[ty + i*8][tx] = in[(size_t)(k0 + ty + i*8)*N + n0 + tx];
    __syncthreads();
    #pragma unroll
    for (int i = 0; i < 4; i++)
        out[(size_t)(n0 + ty + i*8)*K + k0 + tx] = pack_hl(t[tx][ty + i*8]);
}

// ---------------- K4: bf16 hi/lo tensor-core GEMM ----------------
// C[M,N] = A @ B^T   A: [M][K] packed, B: [N][K] packed, C fp32.
// scatter==0: C[r*Ncols + c] = acc
// scatter==1: out[(b*N_ + idxmap[r])*D_ + c] += acc
#define AST 40          // smem k-row stride in u16 (conflict-free for ldmatrix)
#define TILEU16 (128*AST)
__global__ void __launch_bounds__(256) mma_gemm_kernel(
    const uint32_t* __restrict__ A, const uint32_t* __restrict__ B,
    float* __restrict__ C, int M, int Ncols, int K,
    int scatter, const int* __restrict__ idxmap)
{
    __shared__ __align__(16) unsigned short smU[4*TILEU16];   // Ahi|Alo|Bhi|Blo = 40KB
    const uint32_t sbase = (uint32_t)__cvta_generic_to_shared(smU);
    const uint32_t sA   = sbase;
    const uint32_t sB   = sbase + 4*TILEU16;     // byte offset of B region
    const int tid = threadIdx.x;
    const int lane = tid & 31, warp = tid >> 5;
    const int wm = (warp >> 1) * 32;
    const int wn = (warp & 1) * 64;
    const int bm = blockIdx.y * 128, bn = blockIdx.x * 128;

    const uint32_t offA = (uint32_t)(((lane & 15)*AST + (lane >> 4)*8) * 2);
    const uint32_t offB = (uint32_t)(((((lane >> 4)*8) + (lane & 7))*AST + ((lane >> 3) & 1)*8) * 2);

    float acc[2][8][4];
    #pragma unroll
    for (int i = 0; i < 2; i++)
        #pragma unroll
        for (int j = 0; j < 8; j++)
            #pragma unroll
            for (int q = 0; q < 4; q++) acc[i][j][q] = 0.0f;

    for (int k0 = 0; k0 < K; k0 += 32) {
        uint4 av[4], bv[4];
        #pragma unroll
        for (int i = 0; i < 4; i++) {
            int idx = tid + i*256;
            int r = idx >> 3, c4 = idx & 7;
            av[i] = *(const uint4*)(A + (size_t)(bm + r)*K + k0 + c4*4);
            bv[i] = *(const uint4*)(B + (size_t)(bn + r)*K + k0 + c4*4);
        }
        __syncthreads();
        #pragma unroll
        for (int i = 0; i < 4; i++) {
            int idx = tid + i*256;
            int r = idx >> 3, c4 = idx & 7;
            int sb = r*AST + c4*4;
            uint32_t hi01 = prmt_(av[i].x, av[i].y, 0x7632);
            uint32_t hi23 = prmt_(av[i].z, av[i].w, 0x7632);
            uint32_t lo01 = prmt_(av[i].x, av[i].y, 0x5410);
            uint32_t lo23 = prmt_(av[i].z, av[i].w, 0x5410);
            *(uint32_t*)&smU[sb]              = hi01;
            *(uint32_t*)&smU[sb + 2]          = hi23;
            *(uint32_t*)&smU[sb + TILEU16]    = lo01;
            *(uint32_t*)&smU[sb + TILEU16+2]  = lo23;
            hi01 = prmt_(bv[i].x, bv[i].y, 0x7632);
            hi23 = prmt_(bv[i].z, bv[i].w, 0x7632);
            lo01 = prmt_(bv[i].x, bv[i].y, 0x5410);
            lo23 = prmt_(bv[i].z, bv[i].w, 0x5410);
            *(uint32_t*)&smU[sb + 2*TILEU16]   = hi01;
            *(uint32_t*)&smU[sb + 2*TILEU16+2] = hi23;
            *(uint32_t*)&smU[sb + 3*TILEU16]   = lo01;
            *(uint32_t*)&smU[sb + 3*TILEU16+2] = lo23;
        }
        __syncthreads();
        #pragma unroll
        for (int kk = 0; kk < 32; kk += 16) {
            uint32_t ahi[2][4], alo[2][4];
            #pragma unroll
            for (int mi = 0; mi < 2; mi++) {
                uint32_t a = sA + (uint32_t)(((wm + mi*16)*AST + kk) * 2) + offA;
                ldm4(ahi[mi], a);
                ldm4(alo[mi], a + 2*TILEU16);
            }
            #pragma unroll
            for (int np = 0; np < 4; np++) {
                uint32_t bhi[4], blo[4];
                uint32_t ba = sB + (uint32_t)(((wn + np*16)*AST + kk) * 2) + offB;
                ldm4(bhi, ba);
                ldm4(blo, ba + 2*TILEU16);
                #pragma unroll
                for (int mi = 0; mi < 2; mi++) {
                    mma16816(acc[mi][2*np],   ahi[mi], bhi[0], bhi[1]);
                    mma16816(acc[mi][2*np],   ahi[mi], blo[0], blo[1]);
                    mma16816(acc[mi][2*np],   alo[mi], bhi[0], bhi[1]);
                    mma16816(acc[mi][2*np+1], ahi[mi], bhi[2], bhi[3]);
                    mma16816(acc[mi][2*np+1], ahi[mi], blo[2], blo[3]);
                    mma16816(acc[mi][2*np+1], alo[mi], bhi[2], bhi[3]);
                }
            }
        }
        __syncthreads();
    }

    const int rq = lane >> 2, cq = (lane & 3) * 2;
    #pragma unroll
    for (int mi = 0; mi < 2; mi++) {
        #pragma unroll
        for (int ni = 0; ni < 8; ni++) {
            int col = bn + wn + ni*8 + cq;
            int r0 = bm + wm + mi*16 + rq;
            if (!scatter) {
                float2* p0 = (float2*)(C + (size_t)r0*Ncols + col);
                float2* p1 = (float2*)(C + (size_t)(r0+8)*Ncols + col);
                *p0 = make_float2(acc[mi][ni][0], acc[mi][ni][1]);
                *p1 = make_float2(acc[mi][ni][2], acc[mi][ni][3]);
            } else {
                int b0 = r0 >> 10, q0 = r0 & 1023;
                int orow0 = b0*N_ + idxmap[b0*NQ_ + q0];
                float2* p0 = (float2*)(C + (size_t)orow0*D_ + col);
                float2 v0 = *p0; v0.x += acc[mi][ni][0]; v0.y += acc[mi][ni][1]; *p0 = v0;
                int r1 = r0 + 8;
                int b1 = r1 >> 10, q1 = r1 & 1023;
                int orow1 = b1*N_ + idxmap[b1*NQ_ + q1];
                float2* p1 = (float2*)(C + (size_t)orow1*D_ + col);
                float2 v1 = *p1; v1.x += acc[mi][ni][2]; v1.y += acc[mi][ni][3]; *p1 = v1;
            }
        }
    }
}

// ---------------- K5: flash attention (fp32 in, packed out) ----------------
#define KT 64
#define FLASH_SMEM ((KT*DH_*2 + 128*65) * 4)
__global__ void __launch_bounds__(128) flash_kernel(
    const float* __restrict__ Q, const float* __restrict__ K,
    const float* __restrict__ V, uint32_t* __restrict__ O, int mode)
{
    extern __shared__ float sm[];
    float* ks = sm;
    float* vs = sm + KT*DH_;
    float* sc = sm + 2*KT*DH_;
    int tid = threadIdx.x;
    int qRow0, kvRow0, kvLen, qcol, kcol, vcol, ocol;
    if (mode == 0) {
        int h = blockIdx.x & 7, w = (blockIdx.x >> 3) & 63, b = blockIdx.x >> 9;
        qRow0 = b*N_ + w*WIN_; kvRow0 = qRow0; kvLen = WIN_;
        qcol = h*DH_; kcol = h*DH_; vcol = HID_ + h*DH_; ocol = h*DH_;
    } else {
        int h = blockIdx.x & 7, t = (blockIdx.x >> 3) & 7, b = blockIdx.x >> 6;
        qRow0 = b*NQ_ + t*128; kvRow0 = b*NKV_; kvLen = NKV_;
        qcol = h*DH_; kcol = h*2*DH_; vcol = h*2*DH_ + DH_; ocol = h*DH_;
    }
    const int qStride = HID_, kvStride = 2*HID_, oStride = HID_;

    float qr[DH_];
    {
        const float* qp = Q + (size_t)(qRow0 + tid)*qStride + qcol;
        #pragma unroll
        for (int d4 = 0; d4 < 16; d4++) {
            float4 v = *(const float4*)(qp + d4*4);
            qr[d4*4+0] = v.x*SCALE_; qr[d4*4+1] = v.y*SCALE_;
            qr[d4*4+2] = v.z*SCALE_; qr[d4*4+3] = v.w*SCALE_;
        }
    }
    float m = -INFINITY, l = 0.0f;
    float acc[DH_] = {};
    for (int t0 = 0; t0 < kvLen; t0 += KT) {
        #pragma unroll
        for (int i = 0; i < 8; i++) {
            int l4 = tid + i*128;
            int r = l4 >> 4, c4 = l4 & 15;
            const float* kp = K + (size_t)(kvRow0 + t0 + r)*kvStride + kcol;
            const float* vp = V + (size_t)(kvRow0 + t0 + r)*kvStride + vcol;
            *(float4*)&ks[r*DH_ + c4*4] = *(const float4*)(kp + c4*4);
            *(float4*)&vs[r*DH_ + c4*4] = *(const float4*)(vp + c4*4);
        }
        __syncthreads();
        float tmax = -INFINITY;
        #pragma unroll 2
        for (int j = 0; j < KT; j++) {
            float s0 = 0, s1 = 0, s2 = 0, s3 = 0;
            const float4* kp4 = (const float4*)(ks + j*DH_);
            #pragma unroll
            for (int d4 = 0; d4 < 16; d4++) {
                float4 kv4 = kp4[d4];
                s0 = fmaf(qr[d4*4+0], kv4.x, s0);
                s1 = fmaf(qr[d4*4+1], kv4.y, s1);
                s2 = fmaf(qr[d4*4+2], kv4.z, s2);
                s3 = fmaf(qr[d4*4+3], kv4.w, s3);
            }
            float s = (s0 + s1) + (s2 + s3);
            sc[tid*65 + j] = s;
            tmax = fmaxf(tmax, s);
        }
        float mn = fmaxf(m, tmax);
        float corr = expf(m - mn);
        l *= corr;
        #pragma unroll
        for (int d = 0; d < DH_; d++) acc[d] *= corr;
        #pragma unroll 2
        for (int j = 0; j < KT; j++) {
            float p = expf(sc[tid*65 + j] - mn);
            l += p;
            const float4* vp4 = (const float4*)(vs + j*DH_);
            #pragma unroll
            for (int d4 = 0; d4 < 16; d4++) {
                float4 vv = vp4[d4];
                acc[d4*4+0] = fmaf(p, vv.x, acc[d4*4+0]);
                acc[d4*4+1] = fmaf(p, vv.y, acc[d4*4+1]);
                acc[d4*4+2] = fmaf(p, vv.z, acc[d4*4+2]);
                acc[d4*4+3] = fmaf(p, vv.w, acc[d4*4+3]);
            }
        }
        m = mn;
        __syncthreads();
    }
    float invl = 1.0f / l;
    uint32_t* op = O + (size_t)(qRow0 + tid)*oStride + ocol;
    #pragma unroll
    for (int d4 = 0; d4 < 16; d4++) {
        uint4 o4 = { pack_hl(acc[d4*4+0]*invl), pack_hl(acc[d4*4+1]*invl),
                     pack_hl(acc[d4*4+2]*invl), pack_hl(acc[d4*4+3]*invl) };
        *(uint4*)(op + d4*4) = o4;
    }
}

// ---------------- host launch ----------------
extern "C" void kernel_launch(void* const* d_in, const int* in_sizes, int n_in,
                              void* d_out, int out_size)
{
    const float* x      = (const float*)d_in[0];
    const float* gammaL = (const float*)d_in[1];
    const float* wqL    = (const float*)d_in[2];
    const float* wkvL   = (const float*)d_in[3];
    const float* woL    = (const float*)d_in[4];
    const float* qtok   = (const float*)d_in[5];
    const float* kvtok  = (const float*)d_in[6];
    const float* gammaH = (const float*)d_in[7];
    const float* wqH    = (const float*)d_in[8];
    const float* wkvH   = (const float*)d_in[9];
    const float* woH    = (const float*)d_in[10];
    float* out = (float*)d_out;

    uint32_t *p_xn, *p_ao, *p_xqn, *p_ctxn, *p_aoh;
    uint32_t *p_wqL, *p_wkvL, *p_woL, *p_wqH, *p_wkvH, *p_woH;
    float *p_q, *p_kv, *p_qh, *p_kvh;
    int *p_idxq;
    cudaGetSymbolAddress((void**)&p_xn,   c_xn);
    cudaGetSymbolAddress((void**)&p_ao,   c_ao);
    cudaGetSymbolAddress((void**)&p_xqn,  c_xqn);
    cudaGetSymbolAddress((void**)&p_ctxn, c_ctxn);
    cudaGetSymbolAddress((void**)&p_aoh,  c_aoh);
    cudaGetSymbolAddress((void**)&p_wqL,  c_wqL);
    cudaGetSymbolAddress((void**)&p_wkvL, c_wkvL);
    cudaGetSymbolAddress((void**)&p_woL,  c_woL);
    cudaGetSymbolAddress((void**)&p_wqH,  c_wqH);
    cudaGetSymbolAddress((void**)&p_wkvH, c_wkvH);
    cudaGetSymbolAddress((void**)&p_woH,  c_woH);
    cudaGetSymbolAddress((void**)&p_q,    g_q);
    cudaGetSymbolAddress((void**)&p_kv,   g_kv);
    cudaGetSymbolAddress((void**)&p_qh,   g_qh);
    cudaGetSymbolAddress((void**)&p_kvh,  g_kvh);
    cudaGetSymbolAddress((void**)&p_idxq, g_idxq);

    cudaFuncSetAttribute(routing_kernel, cudaFuncAttributeMaxDynamicSharedMemorySize, 131072);
    cudaFuncSetAttribute(flash_kernel,   cudaFuncAttributeMaxDynamicSharedMemorySize, FLASH_SMEM);

    // light rmsnorm (packed) + routing logits
    prep_kernel<<<ROWS_, 256>>>(x, gammaL, qtok, kvtok);
    // routing
    routing_kernel<<<8, 1024, 131072>>>();
    // weight conversions
    wconvT_kernel<<<dim3(HID_/32,  D_/32),  dim3(32,8)>>>(wqL,  p_wqL,  D_,   HID_);
    wconvT_kernel<<<dim3(2*HID_/32,D_/32),  dim3(32,8)>>>(wkvL, p_wkvL, D_,   2*HID_);
    wconvT_kernel<<<dim3(D_/32,    HID_/32),dim3(32,8)>>>(woL,  p_woL,  HID_, D_);
    wconvT_kernel<<<dim3(HID_/32,  D_/32),  dim3(32,8)>>>(wqH,  p_wqH,  D_,   HID_);
    convert_kernel<<<(2*HID_*D_/4 + 255)/256, 256>>>(wkvH, p_wkvH, 2*HID_*D_/4);
    wconvT_kernel<<<dim3(D_/32,    HID_/32),dim3(32,8)>>>(woH,  p_woH,  HID_, D_);
    // light GEMMs (tensor cores)
    mma_gemm_kernel<<<dim3(HID_/128,   ROWS_/128), 256>>>(p_xn, p_wqL,  p_q,  ROWS_, HID_,   D_, 0, nullptr);
    mma_gemm_kernel<<<dim3(2*HID_/128, ROWS_/128), 256>>>(p_xn, p_wkvL, p_kv, ROWS_, 2*HID_, D_, 0, nullptr);
    // light windowed attention (writes packed ao directly)
    flash_kernel<<<B_*(N_/WIN_)*H_, 128, FLASH_SMEM>>>(p_q, p_kv, p_kv, p_ao, 0);
    // light output projection -> d_out
    mma_gemm_kernel<<<dim3(D_/128, ROWS_/128), 256>>>(p_ao, p_woL, out, ROWS_, D_, HID_, 0, nullptr);
    // heavy gather + rmsnorm (packed)
    gather_norm_kernel<<<B_*NQ_ + B_*NKV_, 256>>>(x, gammaH);
    // heavy GEMMs
    mma_gemm_kernel<<<dim3(HID_/128,   (B_*NQ_)/128),  256>>>(p_xqn,  p_wqH,  p_qh,  B_*NQ_,  HID_,   D_, 0, nullptr);
    mma_gemm_kernel<<<dim3(2*HID_/128, (B_*NKV_)/128), 256>>>(p_ctxn, p_wkvH, p_kvh, B_*NKV_, 2*HID_, D_, 0, nullptr);
    // heavy flash attention (writes packed aoh directly)
    flash_kernel<<<B_*(NQ_/128)*H_, 128, FLASH_SMEM>>>(p_qh, p_kvh, p_kvh, p_aoh, 1);
    // heavy output projection + scatter-add
    mma_gemm_kernel<<<dim3(D_/128, (B_*NQ_)/128), 256>>>(p_aoh, p_woH, out, B_*NQ_, D_, HID_, 1, p_idxq);
}

// round 5
// speedup vs baseline: 2.6377x; 1.8111x over previous
#include <cuda_runtime.h>
#include <cuda_bf16.h>
#include <cstdint>
#include <math.h>

// ---------------- problem constants ----------------
#define B_    4
#define N_    8192
#define D_    1024
#define H_    8
#define DH_   64
#define HID_  512
#define WIN_  128
#define NQ_   1024
#define NKV_  2048
#define NITER_ 50
#define ROWS_ (B_*N_)          // 32768
#define SCALE_ 0.125f

// ---------------- device scratch (packed bf16 hi/lo: u32 = (hi<<16)|lo) ----
__device__ uint32_t c_xn  [ (size_t)ROWS_*D_      ];
__device__ uint32_t c_ao  [ (size_t)ROWS_*HID_    ];
__device__ uint32_t c_xqn [ (size_t)B_*NQ_*D_     ];
__device__ uint32_t c_ctxn[ (size_t)B_*NKV_*D_    ];
__device__ uint32_t c_aoh [ (size_t)B_*NQ_*HID_   ];
__device__ uint32_t c_wqL [ (size_t)HID_*D_   ];
__device__ uint32_t c_wkvL[ (size_t)2*HID_*D_ ];
__device__ uint32_t c_woL [ (size_t)D_*HID_   ];
__device__ uint32_t c_wqH [ (size_t)HID_*D_   ];
__device__ uint32_t c_wkvH[ (size_t)2*HID_*D_ ];
__device__ uint32_t c_woH [ (size_t)D_*HID_   ];
__device__ uint32_t c_q   [ (size_t)ROWS_*HID_    ];
__device__ uint32_t c_kv  [ (size_t)ROWS_*2*HID_  ];
__device__ uint32_t c_qh  [ (size_t)B_*NQ_*HID_   ];
__device__ uint32_t c_kvh [ (size_t)B_*NKV_*2*HID_];
__device__ float g_s   [ (size_t)2*ROWS_       ];
__device__ int   g_idxq[ B_*NQ_  ];
__device__ int   g_idxkv[B_*NKV_ ];

// ---------------- helpers ----------------
__device__ __forceinline__ uint32_t pack_hl(float x) {
    __nv_bfloat16 h = __float2bfloat16(x);
    float r = x - __bfloat162float(h);
    __nv_bfloat16 l = __float2bfloat16(r);
    return ((uint32_t)__bfloat16_as_ushort(h) << 16) | (uint32_t)__bfloat16_as_ushort(l);
}
__device__ __forceinline__ uint32_t prmt_(uint32_t a, uint32_t b, uint32_t s) {
    uint32_t d; asm("prmt.b32 %0,%1,%2,%3;" : "=r"(d) : "r"(a), "r"(b), "r"(s)); return d;
}
__device__ __forceinline__ void ldm4(uint32_t* r, uint32_t saddr) {
    asm volatile("ldmatrix.sync.aligned.m8n8.x4.shared.b16 {%0,%1,%2,%3}, [%4];"
        : "=r"(r[0]), "=r"(r[1]), "=r"(r[2]), "=r"(r[3]) : "r"(saddr));
}
__device__ __forceinline__ void ldm4t(uint32_t* r, uint32_t saddr) {
    asm volatile("ldmatrix.sync.aligned.m8n8.x4.trans.shared.b16 {%0,%1,%2,%3}, [%4];"
        : "=r"(r[0]), "=r"(r[1]), "=r"(r[2]), "=r"(r[3]) : "r"(saddr));
}
__device__ __forceinline__ void mma16816(float* c, const uint32_t* a, uint32_t b0, uint32_t b1) {
    asm volatile("mma.sync.aligned.m16n8k16.row.col.f32.bf16.bf16.f32 "
        "{%0,%1,%2,%3}, {%4,%5,%6,%7}, {%8,%9}, {%0,%1,%2,%3};"
        : "+f"(c[0]), "+f"(c[1]), "+f"(c[2]), "+f"(c[3])
        : "r"(a[0]), "r"(a[1]), "r"(a[2]), "r"(a[3]), "r"(b0), "r"(b1));
}
// packed bf16x2: first source -> upper half
__device__ __forceinline__ uint32_t bf16x2_(float up, float lo) {
    uint32_t r; asm("cvt.rn.bf16x2.f32 %0,%1,%2;" : "=r"(r) : "f"(up), "f"(lo)); return r;
}
// split two f32 (v0 -> lower elem, v1 -> upper elem) into bf16x2 hi + residual-lo
__device__ __forceinline__ void split_hl2(float v0, float v1, uint32_t& hi, uint32_t& lo) {
    hi = bf16x2_(v1, v0);
    float h0 = __uint_as_float(hi << 16);
    float h1 = __uint_as_float(hi & 0xffff0000u);
    lo = bf16x2_(v1 - h1, v0 - h0);
}

// block reduction: op 0 = sum, 1 = max
__device__ __forceinline__ float block_reduce(float v, float* sh, int op) {
    int lane = threadIdx.x & 31, w = threadIdx.x >> 5, nw = blockDim.x >> 5;
    #pragma unroll
    for (int o = 16; o; o >>= 1) {
        float t = __shfl_xor_sync(0xFFFFFFFFu, v, o);
        v = op ? fmaxf(v, t) : (v + t);
    }
    if (lane == 0) sh[w] = v;
    __syncthreads();
    if (w == 0) {
        v = (lane < nw) ? sh[lane] : (op ? -INFINITY : 0.0f);
        #pragma unroll
        for (int o = 16; o; o >>= 1) {
            float t = __shfl_xor_sync(0xFFFFFFFFu, v, o);
            v = op ? fmaxf(v, t) : (v + t);
        }
        if (lane == 0) sh[0] = v;
    }
    __syncthreads();
    v = sh[0];
    __syncthreads();
    return v;
}

// ---------------- K1: light rmsnorm (-> packed) + routing logits ----------------
__global__ void __launch_bounds__(256) prep_kernel(
    const float* __restrict__ x, const float* __restrict__ gamma,
    const float* __restrict__ qtok, const float* __restrict__ kvtok)
{
    __shared__ float sh[32];
    int row = blockIdx.x, tid = threadIdx.x;
    const float4 v  = ((const float4*)(x + (size_t)row*D_))[tid];
    const float4 qt = ((const float4*)qtok)[tid];
    const float4 kt = ((const float4*)kvtok)[tid];
    float ss = v.x*v.x + v.y*v.y + v.z*v.z + v.w*v.w;
    float dq = v.x*qt.x + v.y*qt.y + v.z*qt.z + v.w*qt.w;
    float dk = v.x*kt.x + v.y*kt.y + v.z*kt.z + v.w*kt.w;
    ss = block_reduce(ss, sh, 0);
    dq = block_reduce(dq, sh, 0);
    dk = block_reduce(dk, sh, 0);
    float inv = 32.0f / fmaxf(sqrtf(ss), 1e-12f);
    const float4 g = ((const float4*)gamma)[tid];
    uint4 o;
    o.x = pack_hl(v.x*inv*g.x); o.y = pack_hl(v.y*inv*g.y);
    o.z = pack_hl(v.z*inv*g.z); o.w = pack_hl(v.w*inv*g.w);
    ((uint4*)(c_xn + (size_t)row*D_))[tid] = o;
    if (tid == 0) { g_s[row] = dq; g_s[ROWS_ + row] = dk; }
}

// ---------------- K2: coor-descent + top-k set selection ----------------
__global__ void __launch_bounds__(1024) routing_kernel()
{
    extern __shared__ float smr[];
    float* ss = smr;
    float* bb = smr + N_;
    unsigned long long* keys = (unsigned long long*)(smr + 2*N_);
    __shared__ float sh[32];
    int tid = threadIdx.x;
    int b = blockIdx.x & 3;
    int route = blockIdx.x >> 2;
    const float* sp = g_s + (size_t)route*ROWS_ + (size_t)b*N_;
    for (int i = tid; i < N_; i += 1024) { float v = sp[i]; ss[i] = v; bb[i] = -v; }
    __syncthreads();
    const float logk = route ? logf(2304.0f) : logf(1152.0f);
    float a = 0.0f;
    for (int it = 0; it < NITER_; it++) {
        float lm = -INFINITY;
        for (int i = tid; i < N_; i += 1024) lm = fmaxf(lm, ss[i] + bb[i]);
        float m = block_reduce(lm, sh, 1);
        float lsum = 0.0f;
        for (int i = tid; i < N_; i += 1024) lsum += expf(ss[i] + bb[i] - m);
        float sum = block_reduce(lsum, sh, 0);
        a = logk - (m + logf(sum));
        for (int i = tid; i < N_; i += 1024) bb[i] = -fmaxf(ss[i] + a, 0.0f);
    }
    __syncthreads();
    for (int i = tid; i < N_; i += 1024) {
        float sc = expf(fminf(ss[i] + a, 0.0f));
        keys[i] = ((unsigned long long)__float_as_uint(sc) << 32)
                | (unsigned long long)(0xFFFFFFFFu - (unsigned)i);
    }
    __syncthreads();
    for (int size = 2; size <= N_; size <<= 1) {
        for (int stride = size >> 1; stride > 0; stride >>= 1) {
            #pragma unroll
            for (int r = 0; r < N_/2/1024; r++) {
                int t = tid + r*1024;
                int pos = 2*t - (t & (stride - 1));
                bool dir = ((pos & size) == 0);
                unsigned long long A = keys[pos], Bv = keys[pos + stride];
                if ((A < Bv) == dir) { keys[pos] = Bv; keys[pos + stride] = A; }
            }
            __syncthreads();
        }
    }
    int sel = route ? NKV_ : NQ_;
    unsigned* ids = (unsigned*)bb;
    for (int i = tid; i < sel; i += 1024)
        ids[i] = 0xFFFFFFFFu - (unsigned)(keys[i] & 0xFFFFFFFFull);
    __syncthreads();
    for (int size = 2; size <= sel; size <<= 1) {
        for (int stride = size >> 1; stride > 0; stride >>= 1) {
            if (tid < sel/2) {
                int pos = 2*tid - (tid & (stride - 1));
                bool dir = ((pos & size) != 0);
                unsigned A = ids[pos], Bv = ids[pos + stride];
                if ((A < Bv) == dir) { ids[pos] = Bv; ids[pos + stride] = A; }
            }
            __syncthreads();
        }
    }
    int* outp = route ? (g_idxkv + b*NKV_) : (g_idxq + b*NQ_);
    for (int i = tid; i < sel; i += 1024) outp[i] = (int)ids[i];
}

// ---------------- K3: gather + heavy rmsnorm (-> packed) ----------------
__global__ void __launch_bounds__(256) gather_norm_kernel(
    const float* __restrict__ x, const float* __restrict__ gamma)
{
    __shared__ float sh[32];
    int bid = blockIdx.x, tid = threadIdx.x;
    int b, src; uint32_t* dst;
    if (bid < B_*NQ_) { b = bid >> 10; src = g_idxq[bid];  dst = c_xqn  + (size_t)bid*D_; }
    else { int j = bid - B_*NQ_; b = j >> 11; src = g_idxkv[j]; dst = c_ctxn + (size_t)j*D_; }
    const float4 v = ((const float4*)(x + ((size_t)b*N_ + src)*D_))[tid];
    float ssum = block_reduce(v.x*v.x + v.y*v.y + v.z*v.z + v.w*v.w, sh, 0);
    float inv = 32.0f / fmaxf(sqrtf(ssum), 1e-12f);
    const float4 g = ((const float4*)gamma)[tid];
    uint4 o;
    o.x = pack_hl(v.x*inv*g.x); o.y = pack_hl(v.y*inv*g.y);
    o.z = pack_hl(v.z*inv*g.z); o.w = pack_hl(v.w*inv*g.w);
    ((uint4*)dst)[tid] = o;
}

// ---------------- weight conversion kernels ----------------
__global__ void __launch_bounds__(256) convert_kernel(
    const float* __restrict__ in, uint32_t* __restrict__ out, int n4)
{
    int i = blockIdx.x*256 + threadIdx.x;
    if (i >= n4) return;
    float4 v = ((const float4*)in)[i];
    uint4 o = { pack_hl(v.x), pack_hl(v.y), pack_hl(v.z), pack_hl(v.w) };
    ((uint4*)out)[i] = o;
}
__global__ void __launch_bounds__(256) wconvT_kernel(
    const float* __restrict__ in, uint32_t* __restrict__ out, int K, int N)
{
    __shared__ float t[32][33];
    int tx = threadIdx.x, ty = threadIdx.y;          // 32 x 8
    int n0 = blockIdx.x*32, k0 = blockIdx.y*32;
    #pragma unroll
    for (int i = 0; i < 4; i++)
        t[ty + i*8][tx] = in[(size_t)(k0 + ty + i*8)*N + n0 + tx];
    __syncthreads();
    #pragma unroll
    for (int i = 0; i < 4; i++)
        out[(size_t)(n0 + ty + i*8)*K + k0 + tx] = pack_hl(t[tx][ty + i*8]);
}

// ---------------- K4: bf16 hi/lo tensor-core GEMM ----------------
// C = A @ B^T. mode 0: f32 store. mode 1: packed-u32 store. mode 2: f32 scatter-add via idxmap.
#define AST 40
#define TILEU16 (128*AST)
__global__ void __launch_bounds__(256) mma_gemm_kernel(
    const uint32_t* __restrict__ A, const uint32_t* __restrict__ B,
    float* __restrict__ C, int M, int Ncols, int K,
    int mode, const int* __restrict__ idxmap)
{
    __shared__ __align__(16) unsigned short smU[4*TILEU16];
    const uint32_t sbase = (uint32_t)__cvta_generic_to_shared(smU);
    const uint32_t sA   = sbase;
    const uint32_t sB   = sbase + 4*TILEU16;
    const int tid = threadIdx.x;
    const int lane = tid & 31, warp = tid >> 5;
    const int wm = (warp >> 1) * 32;
    const int wn = (warp & 1) * 64;
    const int bm = blockIdx.y * 128, bn = blockIdx.x * 128;

    const uint32_t offA = (uint32_t)(((lane & 15)*AST + (lane >> 4)*8) * 2);
    const uint32_t offB = (uint32_t)(((((lane >> 4)*8) + (lane & 7))*AST + ((lane >> 3) & 1)*8) * 2);

    float acc[2][8][4];
    #pragma unroll
    for (int i = 0; i < 2; i++)
        #pragma unroll
        for (int j = 0; j < 8; j++)
            #pragma unroll
            for (int q = 0; q < 4; q++) acc[i][j][q] = 0.0f;

    for (int k0 = 0; k0 < K; k0 += 32) {
        uint4 av[4], bv[4];
        #pragma unroll
        for (int i = 0; i < 4; i++) {
            int idx = tid + i*256;
            int r = idx >> 3, c4 = idx & 7;
            av[i] = *(const uint4*)(A + (size_t)(bm + r)*K + k0 + c4*4);
            bv[i] = *(const uint4*)(B + (size_t)(bn + r)*K + k0 + c4*4);
        }
        __syncthreads();
        #pragma unroll
        for (int i = 0; i < 4; i++) {
            int idx = tid + i*256;
            int r = idx >> 3, c4 = idx & 7;
            int sb = r*AST + c4*4;
            uint32_t hi01 = prmt_(av[i].x, av[i].y, 0x7632);
            uint32_t hi23 = prmt_(av[i].z, av[i].w, 0x7632);
            uint32_t lo01 = prmt_(av[i].x, av[i].y, 0x5410);
            uint32_t lo23 = prmt_(av[i].z, av[i].w, 0x5410);
            *(uint32_t*)&smU[sb]              = hi01;
            *(uint32_t*)&smU[sb + 2]          = hi23;
            *(uint32_t*)&smU[sb + TILEU16]    = lo01;
            *(uint32_t*)&smU[sb + TILEU16+2]  = lo23;
            hi01 = prmt_(bv[i].x, bv[i].y, 0x7632);
            hi23 = prmt_(bv[i].z, bv[i].w, 0x7632);
            lo01 = prmt_(bv[i].x, bv[i].y, 0x5410);
            lo23 = prmt_(bv[i].z, bv[i].w, 0x5410);
            *(uint32_t*)&smU[sb + 2*TILEU16]   = hi01;
            *(uint32_t*)&smU[sb + 2*TILEU16+2] = hi23;
            *(uint32_t*)&smU[sb + 3*TILEU16]   = lo01;
            *(uint32_t*)&smU[sb + 3*TILEU16+2] = lo23;
        }
        __syncthreads();
        #pragma unroll
        for (int kk = 0; kk < 32; kk += 16) {
            uint32_t ahi[2][4], alo[2][4];
            #pragma unroll
            for (int mi = 0; mi < 2; mi++) {
                uint32_t a = sA + (uint32_t)(((wm + mi*16)*AST + kk) * 2) + offA;
                ldm4(ahi[mi], a);
                ldm4(alo[mi], a + 2*TILEU16);
            }
            #pragma unroll
            for (int np = 0; np < 4; np++) {
                uint32_t bhi[4], blo[4];
                uint32_t ba = sB + (uint32_t)(((wn + np*16)*AST + kk) * 2) + offB;
                ldm4(bhi, ba);
                ldm4(blo, ba + 2*TILEU16);
                #pragma unroll
                for (int mi = 0; mi < 2; mi++) {
                    mma16816(acc[mi][2*np],   ahi[mi], bhi[0], bhi[1]);
                    mma16816(acc[mi][2*np],   ahi[mi], blo[0], blo[1]);
                    mma16816(acc[mi][2*np],   alo[mi], bhi[0], bhi[1]);
                    mma16816(acc[mi][2*np+1], ahi[mi], bhi[2], bhi[3]);
                    mma16816(acc[mi][2*np+1], ahi[mi], blo[2], blo[3]);
                    mma16816(acc[mi][2*np+1], alo[mi], bhi[2], bhi[3]);
                }
            }
        }
        __syncthreads();
    }

    const int rq = lane >> 2, cq = (lane & 3) * 2;
    #pragma unroll
    for (int mi = 0; mi < 2; mi++) {
        #pragma unroll
        for (int ni = 0; ni < 8; ni++) {
            int col = bn + wn + ni*8 + cq;
            int r0 = bm + wm + mi*16 + rq;
            if (mode == 0) {
                float2* p0 = (float2*)(C + (size_t)r0*Ncols + col);
                float2* p1 = (float2*)(C + (size_t)(r0+8)*Ncols + col);
                *p0 = make_float2(acc[mi][ni][0], acc[mi][ni][1]);
                *p1 = make_float2(acc[mi][ni][2], acc[mi][ni][3]);
            } else if (mode == 1) {
                uint32_t* U = (uint32_t*)C;
                uint2* p0 = (uint2*)(U + (size_t)r0*Ncols + col);
                uint2* p1 = (uint2*)(U + (size_t)(r0+8)*Ncols + col);
                *p0 = make_uint2(pack_hl(acc[mi][ni][0]), pack_hl(acc[mi][ni][1]));
                *p1 = make_uint2(pack_hl(acc[mi][ni][2]), pack_hl(acc[mi][ni][3]));
            } else {
                int b0 = r0 >> 10, q0 = r0 & 1023;
                int orow0 = b0*N_ + idxmap[b0*NQ_ + q0];
                float2* p0 = (float2*)(C + (size_t)orow0*D_ + col);
                float2 v0 = *p0; v0.x += acc[mi][ni][0]; v0.y += acc[mi][ni][1]; *p0 = v0;
                int r1 = r0 + 8;
                int b1 = r1 >> 10, q1 = r1 & 1023;
                int orow1 = b1*N_ + idxmap[b1*NQ_ + q1];
                float2* p1 = (float2*)(C + (size_t)orow1*D_ + col);
                float2 v1 = *p1; v1.x += acc[mi][ni][2]; v1.y += acc[mi][ni][3]; *p1 = v1;
            }
        }
    }
}

// ---------------- K5: tensor-core flash attention ----------------
// 128 threads = 4 warps; warp owns 32 q rows. KV tiles of 64.
// Inputs packed u32 hi/lo; output packed u32.
#define FST 72                      // smem row stride (u16)
#define QPL (128*FST)               // Q plane size (u16)
#define KPL (64*FST)                // K/V plane size (u16)
#define FLASH2_SMEM ((2*QPL + 4*KPL)*2)   // bytes = 73728
__global__ void __launch_bounds__(128) flash_mma_kernel(
    const uint32_t* __restrict__ Q, const uint32_t* __restrict__ KV,
    uint32_t* __restrict__ O, int mode)
{
    extern __shared__ unsigned short fsm[];
    const uint32_t sb = (uint32_t)__cvta_generic_to_shared(fsm);
    const uint32_t sQhi = sb;
    const uint32_t sQlo = sb + QPL*2;
    const uint32_t sKhi = sb + 2*QPL*2;
    const uint32_t sKlo = sKhi + KPL*2;
    const uint32_t sVhi = sKlo + KPL*2;
    const uint32_t sVlo = sVhi + KPL*2;
    unsigned short* mQhi = fsm;
    unsigned short* mQlo = fsm + QPL;
    unsigned short* mKhi = fsm + 2*QPL;
    unsigned short* mKlo = mKhi + KPL;
    unsigned short* mVhi = mKlo + KPL;
    unsigned short* mVlo = mVhi + KPL;

    const int tid = threadIdx.x;
    const int lane = tid & 31, warp = tid >> 5;
    const int wm = warp * 32;

    int qRow0, kvRow0, kvLen, qcol, kcol, vcol, ocol;
    if (mode == 0) {
        int h = blockIdx.x & 7, w = (blockIdx.x >> 3) & 63, b = blockIdx.x >> 9;
        qRow0 = b*N_ + w*WIN_; kvRow0 = qRow0; kvLen = WIN_;
        qcol = h*DH_; kcol = h*DH_; vcol = HID_ + h*DH_; ocol = h*DH_;
    } else {
        int h = blockIdx.x & 7, t = (blockIdx.x >> 3) & 7, b = blockIdx.x >> 6;
        qRow0 = b*NQ_ + t*128; kvRow0 = b*NKV_; kvLen = NKV_;
        qcol = h*DH_; kcol = h*2*DH_; vcol = h*2*DH_ + DH_; ocol = h*DH_;
    }
    const int qStride = HID_, kvStride = 2*HID_, oStride = HID_;

    // stage Q (128 x 64 u32) into hi/lo planes
    for (int i = tid; i < 128*16; i += 128) {
        int r = i >> 4, c4 = (i & 15) * 4;
        uint4 v = *(const uint4*)(Q + (size_t)(qRow0 + r)*qStride + qcol + c4);
        int si = r*FST + c4;
        *(uint32_t*)&mQhi[si]     = prmt_(v.x, v.y, 0x7632);
        *(uint32_t*)&mQhi[si + 2] = prmt_(v.z, v.w, 0x7632);
        *(uint32_t*)&mQlo[si]     = prmt_(v.x, v.y, 0x5410);
        *(uint32_t*)&mQlo[si + 2] = prmt_(v.z, v.w, 0x5410);
    }

    const uint32_t offA = (uint32_t)(((lane & 15)*FST + (lane >> 4)*8) * 2);
    const uint32_t offB = (uint32_t)(((((lane >> 4)*8) + (lane & 7))*FST + ((lane >> 3) & 1)*8) * 2);

    float accO[2][8][4];
    #pragma unroll
    for (int i = 0; i < 2; i++)
        #pragma unroll
        for (int j = 0; j < 8; j++)
            #pragma unroll
            for (int q = 0; q < 4; q++) accO[i][j][q] = 0.0f;
    float mrow[2][2] = {{-INFINITY,-INFINITY},{-INFINITY,-INFINITY}};
    float lrow[2][2] = {{0.0f,0.0f},{0.0f,0.0f}};

    for (int t0 = 0; t0 < kvLen; t0 += 64) {
        __syncthreads();
        // stage K/V tile (64 x 64 u32 each)
        for (int i = tid; i < 64*16; i += 128) {
            int r = i >> 4, c4 = (i & 15) * 4;
            int si = r*FST + c4;
            uint4 kv4 = *(const uint4*)(KV + (size_t)(kvRow0 + t0 + r)*kvStride + kcol + c4);
            *(uint32_t*)&mKhi[si]     = prmt_(kv4.x, kv4.y, 0x7632);
            *(uint32_t*)&mKhi[si + 2] = prmt_(kv4.z, kv4.w, 0x7632);
            *(uint32_t*)&mKlo[si]     = prmt_(kv4.x, kv4.y, 0x5410);
            *(uint32_t*)&mKlo[si + 2] = prmt_(kv4.z, kv4.w, 0x5410);
            uint4 vv4 = *(const uint4*)(KV + (size_t)(kvRow0 + t0 + r)*kvStride + vcol + c4);
            *(uint32_t*)&mVhi[si]     = prmt_(vv4.x, vv4.y, 0x7632);
            *(uint32_t*)&mVhi[si + 2] = prmt_(vv4.z, vv4.w, 0x7632);
            *(uint32_t*)&mVlo[si]     = prmt_(vv4.x, vv4.y, 0x5410);
            *(uint32_t*)&mVlo[si + 2] = prmt_(vv4.z, vv4.w, 0x5410);
        }
        __syncthreads();

        // S = Q K^T  (m32 x n64, k=64), 3-pass hi/lo
        float accS[2][8][4];
        #pragma unroll
        for (int i = 0; i < 2; i++)
            #pragma unroll
            for (int j = 0; j < 8; j++)
                #pragma unroll
                for (int q = 0; q < 4; q++) accS[i][j][q] = 0.0f;
        #pragma unroll
        for (int kc = 0; kc < 4; kc++) {
            uint32_t ahi[2][4], alo[2][4];
            #pragma unroll
            for (int mi = 0; mi < 2; mi++) {
                uint32_t ad = sQhi + (uint32_t)(((wm + mi*16)*FST + kc*16) * 2) + offA;
                ldm4(ahi[mi], ad);
                ldm4(alo[mi], ad + QPL*2);
            }
            #pragma unroll
            for (int np = 0; np < 4; np++) {
                uint32_t bhi[4], blo[4];
                uint32_t bd = sKhi + (uint32_t)((np*16*FST + kc*16) * 2) + offB;
                ldm4(bhi, bd);
                ldm4(blo, bd + KPL*2);
                #pragma unroll
                for (int mi = 0; mi < 2; mi++) {
                    mma16816(accS[mi][2*np],   ahi[mi], bhi[0], bhi[1]);
                    mma16816(accS[mi][2*np],   ahi[mi], blo[0], blo[1]);
                    mma16816(accS[mi][2*np],   alo[mi], bhi[0], bhi[1]);
                    mma16816(accS[mi][2*np+1], ahi[mi], bhi[2], bhi[3]);
                    mma16816(accS[mi][2*np+1], ahi[mi], blo[2], blo[3]);
                    mma16816(accS[mi][2*np+1], alo[mi], bhi[2], bhi[3]);
                }
            }
        }

        // softmax update (rows: g = lane>>2 and g+8 within each mi frag)
        #pragma unroll
        for (int mi = 0; mi < 2; mi++) {
            float t0m = -INFINITY, t1m = -INFINITY;
            #pragma unroll
            for (int nt = 0; nt < 8; nt++) {
                accS[mi][nt][0] *= SCALE_; accS[mi][nt][1] *= SCALE_;
                accS[mi][nt][2] *= SCALE_; accS[mi][nt][3] *= SCALE_;
                t0m = fmaxf(t0m, fmaxf(accS[mi][nt][0], accS[mi][nt][1]));
                t1m = fmaxf(t1m, fmaxf(accS[mi][nt][2], accS[mi][nt][3]));
            }
            t0m = fmaxf(t0m, __shfl_xor_sync(0xFFFFFFFFu, t0m, 1));
            t0m = fmaxf(t0m, __shfl_xor_sync(0xFFFFFFFFu, t0m, 2));
            t1m = fmaxf(t1m, __shfl_xor_sync(0xFFFFFFFFu, t1m, 1));
            t1m = fmaxf(t1m, __shfl_xor_sync(0xFFFFFFFFu, t1m, 2));
            float mn0 = fmaxf(mrow[mi][0], t0m);
            float mn1 = fmaxf(mrow[mi][1], t1m);
            float corr0 = expf(mrow[mi][0] - mn0);
            float corr1 = expf(mrow[mi][1] - mn1);
            float rs0 = 0.0f, rs1 = 0.0f;
            #pragma unroll
            for (int nt = 0; nt < 8; nt++) {
                accS[mi][nt][0] = expf(accS[mi][nt][0] - mn0);
                accS[mi][nt][1] = expf(accS[mi][nt][1] - mn0);
                accS[mi][nt][2] = expf(accS[mi][nt][2] - mn1);
                accS[mi][nt][3] = expf(accS[mi][nt][3] - mn1);
                rs0 += accS[mi][nt][0] + accS[mi][nt][1];
                rs1 += accS[mi][nt][2] + accS[mi][nt][3];
                accO[mi][nt][0] *= corr0; accO[mi][nt][1] *= corr0;
                accO[mi][nt][2] *= corr1; accO[mi][nt][3] *= corr1;
            }
            rs0 += __shfl_xor_sync(0xFFFFFFFFu, rs0, 1);
            rs0 += __shfl_xor_sync(0xFFFFFFFFu, rs0, 2);
            rs1 += __shfl_xor_sync(0xFFFFFFFFu, rs1, 1);
            rs1 += __shfl_xor_sync(0xFFFFFFFFu, rs1, 2);
            lrow[mi][0] = lrow[mi][0]*corr0 + rs0;
            lrow[mi][1] = lrow[mi][1]*corr1 + rs1;
            mrow[mi][0] = mn0; mrow[mi][1] = mn1;
        }

        // O += P V  (k = kv 64, n = dh 64), 3-pass hi/lo; P from registers
        #pragma unroll
        for (int kc = 0; kc < 4; kc++) {
            uint32_t pHi[2][4], pLo[2][4];
            #pragma unroll
            for (int mi = 0; mi < 2; mi++) {
                int te = 2*kc, to = 2*kc + 1;
                split_hl2(accS[mi][te][0], accS[mi][te][1], pHi[mi][0], pLo[mi][0]);
                split_hl2(accS[mi][te][2], accS[mi][te][3], pHi[mi][1], pLo[mi][1]);
                split_hl2(accS[mi][to][0], accS[mi][to][1], pHi[mi][2], pLo[mi][2]);
                split_hl2(accS[mi][to][2], accS[mi][to][3], pHi[mi][3], pLo[mi][3]);
            }
            #pragma unroll
            for (int nt = 0; nt < 4; nt++) {
                uint32_t vhi[4], vlo[4];
                uint32_t vd = sVhi + (uint32_t)((kc*16*FST + nt*16) * 2) + offA;
                ldm4t(vhi, vd);
                ldm4t(vlo, vd + KPL*2);
                #pragma unroll
                for (int mi = 0; mi < 2; mi++) {
                    mma16816(accO[mi][2*nt],   pHi[mi], vhi[0], vhi[1]);
                    mma16816(accO[mi][2*nt],   pHi[mi], vlo[0], vlo[1]);
                    mma16816(accO[mi][2*nt],   pLo[mi], vhi[0], vhi[1]);
                    mma16816(accO[mi][2*nt+1], pHi[mi], vhi[2], vhi[3]);
                    mma16816(accO[mi][2*nt+1], pHi[mi], vlo[2], vlo[3]);
                    mma16816(accO[mi][2*nt+1], pLo[mi], vhi[2], vhi[3]);
                }
            }
        }
    }

    // epilogue: normalize and store packed
    const int g = lane >> 2, q2 = (lane & 3) * 2;
    #pragma unroll
    for (int mi = 0; mi < 2; mi++) {
        float inv0 = 1.0f / lrow[mi][0];
        float inv1 = 1.0f / lrow[mi][1];
        int r0 = qRow0 + wm + mi*16 + g;
        #pragma unroll
        for (int nt = 0; nt < 8; nt++) {
            int col = ocol + nt*8 + q2;
            *(uint2*)(O + (size_t)r0*oStride + col) =
                make_uint2(pack_hl(accO[mi][nt][0]*inv0), pack_hl(accO[mi][nt][1]*inv0));
            *(uint2*)(O + (size_t)(r0+8)*oStride + col) =
                make_uint2(pack_hl(accO[mi][nt][2]*inv1), pack_hl(accO[mi][nt][3]*inv1));
        }
    }
}

// ---------------- host launch ----------------
extern "C" void kernel_launch(void* const* d_in, const int* in_sizes, int n_in,
                              void* d_out, int out_size)
{
    const float* x      = (const float*)d_in[0];
    const float* gammaL = (const float*)d_in[1];
    const float* wqL    = (const float*)d_in[2];
    const float* wkvL   = (const float*)d_in[3];
    const float* woL    = (const float*)d_in[4];
    const float* qtok   = (const float*)d_in[5];
    const float* kvtok  = (const float*)d_in[6];
    const float* gammaH = (const float*)d_in[7];
    const float* wqH    = (const float*)d_in[8];
    const float* wkvH   = (const float*)d_in[9];
    const float* woH    = (const float*)d_in[10];
    float* out = (float*)d_out;

    uint32_t *p_xn, *p_ao, *p_xqn, *p_ctxn, *p_aoh;
    uint32_t *p_wqL, *p_wkvL, *p_woL, *p_wqH, *p_wkvH, *p_woH;
    uint32_t *p_q, *p_kv, *p_qh, *p_kvh;
    int *p_idxq;
    cudaGetSymbolAddress((void**)&p_xn,   c_xn);
    cudaGetSymbolAddress((void**)&p_ao,   c_ao);
    cudaGetSymbolAddress((void**)&p_xqn,  c_xqn);
    cudaGetSymbolAddress((void**)&p_ctxn, c_ctxn);
    cudaGetSymbolAddress((void**)&p_aoh,  c_aoh);
    cudaGetSymbolAddress((void**)&p_wqL,  c_wqL);
    cudaGetSymbolAddress((void**)&p_wkvL, c_wkvL);
    cudaGetSymbolAddress((void**)&p_woL,  c_woL);
    cudaGetSymbolAddress((void**)&p_wqH,  c_wqH);
    cudaGetSymbolAddress((void**)&p_wkvH, c_wkvH);
    cudaGetSymbolAddress((void**)&p_woH,  c_woH);
    cudaGetSymbolAddress((void**)&p_q,    c_q);
    cudaGetSymbolAddress((void**)&p_kv,   c_kv);
    cudaGetSymbolAddress((void**)&p_qh,   c_qh);
    cudaGetSymbolAddress((void**)&p_kvh,  c_kvh);
    cudaGetSymbolAddress((void**)&p_idxq, g_idxq);

    cudaFuncSetAttribute(routing_kernel,  cudaFuncAttributeMaxDynamicSharedMemorySize, 131072);
    cudaFuncSetAttribute(flash_mma_kernel, cudaFuncAttributeMaxDynamicSharedMemorySize, FLASH2_SMEM);

    // light rmsnorm (packed) + routing logits
    prep_kernel<<<ROWS_, 256>>>(x, gammaL, qtok, kvtok);
    // routing
    routing_kernel<<<8, 1024, 131072>>>();
    // weight conversions
    wconvT_kernel<<<dim3(HID_/32,  D_/32),  dim3(32,8)>>>(wqL,  p_wqL,  D_,   HID_);
    wconvT_kernel<<<dim3(2*HID_/32,D_/32),  dim3(32,8)>>>(wkvL, p_wkvL, D_,   2*HID_);
    wconvT_kernel<<<dim3(D_/32,    HID_/32),dim3(32,8)>>>(woL,  p_woL,  HID_, D_);
    wconvT_kernel<<<dim3(HID_/32,  D_/32),  dim3(32,8)>>>(wqH,  p_wqH,  D_,   HID_);
    convert_kernel<<<(2*HID_*D_/4 + 255)/256, 256>>>(wkvH, p_wkvH, 2*HID_*D_/4);
    wconvT_kernel<<<dim3(D_/32,    HID_/32),dim3(32,8)>>>(woH,  p_woH,  HID_, D_);
    // light GEMMs (tensor cores, packed outputs)
    mma_gemm_kernel<<<dim3(HID_/128,   ROWS_/128), 256>>>(p_xn, p_wqL,  (float*)p_q,  ROWS_, HID_,   D_, 1, nullptr);
    mma_gemm_kernel<<<dim3(2*HID_/128, ROWS_/128), 256>>>(p_xn, p_wkvL, (float*)p_kv, ROWS_, 2*HID_, D_, 1, nullptr);
    // light windowed attention (tensor cores)
    flash_mma_kernel<<<B_*(N_/WIN_)*H_, 128, FLASH2_SMEM>>>(p_q, p_kv, p_ao, 0);
    // light output projection -> d_out
    mma_gemm_kernel<<<dim3(D_/128, ROWS_/128), 256>>>(p_ao, p_woL, out, ROWS_, D_, HID_, 0, nullptr);
    // heavy gather + rmsnorm (packed)
    gather_norm_kernel<<<B_*NQ_ + B_*NKV_, 256>>>(x, gammaH);
    // heavy GEMMs (packed outputs)
    mma_gemm_kernel<<<dim3(HID_/128,   (B_*NQ_)/128),  256>>>(p_xqn,  p_wqH,  (float*)p_qh,  B_*NQ_,  HID_,   D_, 1, nullptr);
    mma_gemm_kernel<<<dim3(2*HID_/128, (B_*NKV_)/128), 256>>>(p_ctxn, p_wkvH, (float*)p_kvh, B_*NKV_, 2*HID_, D_, 1, nullptr);
    // heavy flash attention (tensor cores)
    flash_mma_kernel<<<B_*(NQ_/128)*H_, 128, FLASH2_SMEM>>>(p_qh, p_kvh, p_aoh, 1);
    // heavy output projection + scatter-add
    mma_gemm_kernel<<<dim3(D_/128, (B_*NQ_)/128), 256>>>(p_aoh, p_woH, out, B_*NQ_, D_, HID_, 2, p_idxq);
}